// round 3
// baseline (speedup 1.0000x reference)
#include <cuda_runtime.h>
#include <math.h>

// Problem dims
#define BB    128
#define NN    256
#define DD    256
#define MSGD  64
#define CDD   32
#define KK    8
#define H1D   128
#define H2D   256
#define BN    (BB*NN)   // 32768

// -------- device scratch (no allocations allowed) --------
__device__ float g_W2p[H1D*MSGD];           // composed W2@Wc@Wd  (128x64)
__device__ float g_b2p[MSGD];               // composed bias
__device__ float g_h   [(long)BN*H1D];      // 16.8 MB
__device__ float g_msgs[(long)BN*MSGD];     // 8 MB
__device__ float g_tmp [(long)BN*DD];       // 33.5 MB
__device__ float g_scores[(long)BB*NN*NN];  // 33.5 MB
__device__ float g_agg [(long)BN*MSGD];     // 8 MB
__device__ float g_r   [(long)BN*H2D];      // 33.5 MB

// ============================================================
// 0) Compose W2' = W2@Wc@Wd, b2' = b2@Wc@Wd + bc@Wd + bd
// ============================================================
__global__ void prep_kernel(const float* __restrict__ W2, const float* __restrict__ b2,
                            const float* __restrict__ Wc, const float* __restrict__ bc,
                            const float* __restrict__ Wd, const float* __restrict__ bd) {
    __shared__ float bbuf[CDD];
    int t = threadIdx.x; // 128 threads: one per H1 row
    float T[CDD];
    #pragma unroll
    for (int c = 0; c < CDD; c++) T[c] = 0.f;
    for (int m = 0; m < MSGD; m++) {
        float w = W2[t*MSGD + m];
        #pragma unroll
        for (int c = 0; c < CDD; c++) T[c] += w * Wc[m*CDD + c];
    }
    for (int mm = 0; mm < MSGD; mm++) {
        float acc = 0.f;
        #pragma unroll
        for (int c = 0; c < CDD; c++) acc += T[c] * Wd[c*MSGD + mm];
        g_W2p[t*MSGD + mm] = acc;
    }
    if (t < CDD) {
        float acc = bc[t];
        for (int m = 0; m < MSGD; m++) acc += b2[m] * Wc[m*CDD + t];
        bbuf[t] = acc;
    }
    __syncthreads();
    if (t < MSGD) {
        float acc = bd[t];
        #pragma unroll
        for (int c = 0; c < CDD; c++) acc += bbuf[c] * Wd[c*MSGD + t];
        g_b2p[t] = acc;
    }
}

// ============================================================
// Canonical 128 x BNt x 16 SGEMM, 8x8 register tiles.
//   A: row-major (lda = K-stride), loaded transposed into As[k][m]
//   B: row-major (ldb = N-stride), NN layout
//   BIASV: add per-column bias vector; RELU: apply relu
// ============================================================
#define BM  128
#define BK  16

template<int BNt, bool RELU, bool BIASV>
__global__ __launch_bounds__(BNt*2, 2) void sgemm_nn(
    const float* __restrict__ A, int lda,
    const float* __restrict__ Bw, int ldb,
    float* __restrict__ C, int ldc, int Kdim,
    const float* __restrict__ bias)
{
    constexpr int NTH = BNt * 2;           // 256 (BNt=128) or 128 (BNt=64)
    constexpr int APT = (BM*BK/4) / NTH;   // float4 A loads per thread
    constexpr int BPT = (BK*BNt/4) / NTH;  // float4 B loads per thread
    __shared__ float As[BK][BM];
    __shared__ float Bs[BK][BNt];

    const int tid = threadIdx.x;
    const int tx  = tid % (BNt/8);
    const int ty  = tid / (BNt/8);
    const long bm = (long)blockIdx.y * BM;
    const int  bn = blockIdx.x * BNt;

    float4 pa[APT], pb[BPT];
    // --- load first tile ---
    #pragma unroll
    for (int i = 0; i < APT; i++) {
        int idx = tid + i*NTH;
        int r = idx >> 2, kq = (idx & 3) * 4;
        pa[i] = *(const float4*)(A + (bm + r)*lda + kq);
    }
    #pragma unroll
    for (int i = 0; i < BPT; i++) {
        int idx = tid + i*NTH;
        int kk = idx / (BNt/4), c4 = (idx % (BNt/4)) * 4;
        pb[i] = *(const float4*)(Bw + (long)kk*ldb + bn + c4);
    }
    #pragma unroll
    for (int i = 0; i < APT; i++) {
        int idx = tid + i*NTH;
        int r = idx >> 2, kq = (idx & 3) * 4;
        As[kq+0][r] = pa[i].x; As[kq+1][r] = pa[i].y;
        As[kq+2][r] = pa[i].z; As[kq+3][r] = pa[i].w;
    }
    #pragma unroll
    for (int i = 0; i < BPT; i++) {
        int idx = tid + i*NTH;
        int kk = idx / (BNt/4), c4 = (idx % (BNt/4)) * 4;
        *(float4*)(&Bs[kk][c4]) = pb[i];
    }
    __syncthreads();

    float acc[8][8] = {};
    for (int k0 = 0; k0 < Kdim; k0 += BK) {
        const bool has_next = (k0 + BK < Kdim);
        if (has_next) {
            #pragma unroll
            for (int i = 0; i < APT; i++) {
                int idx = tid + i*NTH;
                int r = idx >> 2, kq = (idx & 3) * 4;
                pa[i] = *(const float4*)(A + (bm + r)*lda + k0 + BK + kq);
            }
            #pragma unroll
            for (int i = 0; i < BPT; i++) {
                int idx = tid + i*NTH;
                int kk = idx / (BNt/4), c4 = (idx % (BNt/4)) * 4;
                pb[i] = *(const float4*)(Bw + (long)(k0 + BK + kk)*ldb + bn + c4);
            }
        }
        #pragma unroll
        for (int kk = 0; kk < BK; kk++) {
            float4 a0 = *(const float4*)(&As[kk][ty*8]);
            float4 a1 = *(const float4*)(&As[kk][ty*8+4]);
            float4 b0 = *(const float4*)(&Bs[kk][tx*8]);
            float4 b1 = *(const float4*)(&Bs[kk][tx*8+4]);
            float av[8] = {a0.x,a0.y,a0.z,a0.w,a1.x,a1.y,a1.z,a1.w};
            float bv[8] = {b0.x,b0.y,b0.z,b0.w,b1.x,b1.y,b1.z,b1.w};
            #pragma unroll
            for (int i = 0; i < 8; i++)
                #pragma unroll
                for (int j = 0; j < 8; j++)
                    acc[i][j] += av[i] * bv[j];
        }
        __syncthreads();
        if (has_next) {
            #pragma unroll
            for (int i = 0; i < APT; i++) {
                int idx = tid + i*NTH;
                int r = idx >> 2, kq = (idx & 3) * 4;
                As[kq+0][r] = pa[i].x; As[kq+1][r] = pa[i].y;
                As[kq+2][r] = pa[i].z; As[kq+3][r] = pa[i].w;
            }
            #pragma unroll
            for (int i = 0; i < BPT; i++) {
                int idx = tid + i*NTH;
                int kk = idx / (BNt/4), c4 = (idx % (BNt/4)) * 4;
                *(float4*)(&Bs[kk][c4]) = pb[i];
            }
        }
        __syncthreads();
    }

    float bias0[8] = {};
    if (BIASV) {
        float4 t0 = *(const float4*)(bias + bn + tx*8);
        float4 t1 = *(const float4*)(bias + bn + tx*8 + 4);
        bias0[0]=t0.x; bias0[1]=t0.y; bias0[2]=t0.z; bias0[3]=t0.w;
        bias0[4]=t1.x; bias0[5]=t1.y; bias0[6]=t1.z; bias0[7]=t1.w;
    }
    #pragma unroll
    for (int i = 0; i < 8; i++) {
        long row = bm + ty*8 + i;
        float v[8];
        #pragma unroll
        for (int j = 0; j < 8; j++) {
            v[j] = acc[i][j] + (BIASV ? bias0[j] : 0.f);
            if (RELU) v[j] = fmaxf(v[j], 0.f);
        }
        *(float4*)(C + row*ldc + bn + tx*8)     = make_float4(v[0],v[1],v[2],v[3]);
        *(float4*)(C + row*ldc + bn + tx*8 + 4) = make_float4(v[4],v[5],v[6],v[7]);
    }
}

// ============================================================
// Batched NT SGEMM for scores: per batch 256x256x256
//   C[b][i][j] = sum_k A[b][i][k]*B[b][j][k] + scalar bias
// ============================================================
__global__ __launch_bounds__(256, 2) void sgemm_nt_b(
    const float* __restrict__ A, const float* __restrict__ Bm,
    float* __restrict__ C, const float* __restrict__ bbil)
{
    __shared__ float As[BK][BM];
    __shared__ float Bs[BK][BM];
    const int tid = threadIdx.x;
    const int tx = tid & 15, ty = tid >> 4;
    const int b = blockIdx.z;
    const float* Ab = A  + (long)b * NN * DD;
    const float* Bb = Bm + (long)b * NN * DD;
    float* Cb = C + (long)b * NN * NN;
    const int bi = blockIdx.y * BM;
    const int bj = blockIdx.x * BM;

    float4 pa[2], pb[2];
    #pragma unroll
    for (int i = 0; i < 2; i++) {
        int idx = tid + i*256;
        int r = idx >> 2, kq = (idx & 3) * 4;
        pa[i] = *(const float4*)(Ab + (long)(bi + r)*DD + kq);
        pb[i] = *(const float4*)(Bb + (long)(bj + r)*DD + kq);
    }
    #pragma unroll
    for (int i = 0; i < 2; i++) {
        int idx = tid + i*256;
        int r = idx >> 2, kq = (idx & 3) * 4;
        As[kq+0][r]=pa[i].x; As[kq+1][r]=pa[i].y; As[kq+2][r]=pa[i].z; As[kq+3][r]=pa[i].w;
        Bs[kq+0][r]=pb[i].x; Bs[kq+1][r]=pb[i].y; Bs[kq+2][r]=pb[i].z; Bs[kq+3][r]=pb[i].w;
    }
    __syncthreads();

    float acc[8][8] = {};
    for (int k0 = 0; k0 < DD; k0 += BK) {
        const bool has_next = (k0 + BK < DD);
        if (has_next) {
            #pragma unroll
            for (int i = 0; i < 2; i++) {
                int idx = tid + i*256;
                int r = idx >> 2, kq = (idx & 3) * 4;
                pa[i] = *(const float4*)(Ab + (long)(bi + r)*DD + k0 + BK + kq);
                pb[i] = *(const float4*)(Bb + (long)(bj + r)*DD + k0 + BK + kq);
            }
        }
        #pragma unroll
        for (int kk = 0; kk < BK; kk++) {
            float4 a0 = *(const float4*)(&As[kk][ty*8]);
            float4 a1 = *(const float4*)(&As[kk][ty*8+4]);
            float4 b0 = *(const float4*)(&Bs[kk][tx*8]);
            float4 b1 = *(const float4*)(&Bs[kk][tx*8+4]);
            float av[8] = {a0.x,a0.y,a0.z,a0.w,a1.x,a1.y,a1.z,a1.w};
            float bv[8] = {b0.x,b0.y,b0.z,b0.w,b1.x,b1.y,b1.z,b1.w};
            #pragma unroll
            for (int i = 0; i < 8; i++)
                #pragma unroll
                for (int j = 0; j < 8; j++)
                    acc[i][j] += av[i] * bv[j];
        }
        __syncthreads();
        if (has_next) {
            #pragma unroll
            for (int i = 0; i < 2; i++) {
                int idx = tid + i*256;
                int r = idx >> 2, kq = (idx & 3) * 4;
                As[kq+0][r]=pa[i].x; As[kq+1][r]=pa[i].y; As[kq+2][r]=pa[i].z; As[kq+3][r]=pa[i].w;
                Bs[kq+0][r]=pb[i].x; Bs[kq+1][r]=pb[i].y; Bs[kq+2][r]=pb[i].z; Bs[kq+3][r]=pb[i].w;
            }
        }
        __syncthreads();
    }
    const float bv = *bbil;
    #pragma unroll
    for (int i = 0; i < 8; i++) {
        int row = bi + ty*8 + i;
        *(float4*)(Cb + (long)row*NN + bj + tx*8) =
            make_float4(acc[i][0]+bv, acc[i][1]+bv, acc[i][2]+bv, acc[i][3]+bv);
        *(float4*)(Cb + (long)row*NN + bj + tx*8 + 4) =
            make_float4(acc[i][4]+bv, acc[i][5]+bv, acc[i][6]+bv, acc[i][7]+bv);
    }
}

// ============================================================
// Receiver stage-1 GEMM with virtual A = concat(obs[.,0:256], agg[.,0:64])
//   r = relu(Acat @ Wr1 + br1)  : M=32768, N=256, K=320
// ============================================================
__global__ __launch_bounds__(256, 2) void sgemm_comb(
    const float* __restrict__ obs, const float* __restrict__ agg,
    const float* __restrict__ Wr1, const float* __restrict__ br1,
    float* __restrict__ R)
{
    __shared__ float As[BK][BM];
    __shared__ float Bs[BK][BM];
    const int tid = threadIdx.x;
    const int tx = tid & 15, ty = tid >> 4;
    const long bm = (long)blockIdx.y * BM;
    const int  bn = blockIdx.x * BM;
    const int Kdim = DD + MSGD; // 320

    float4 pa[2], pb[2];
    auto ldA = [&](int i, int k0) {
        int idx = tid + i*256;
        int r = idx >> 2, kq = (idx & 3) * 4;
        int k = k0 + kq;
        if (k < DD) return *(const float4*)(obs + (bm + r)*DD + k);
        else        return *(const float4*)(agg + (bm + r)*MSGD + (k - DD));
    };
    #pragma unroll
    for (int i = 0; i < 2; i++) pa[i] = ldA(i, 0);
    #pragma unroll
    for (int i = 0; i < 2; i++) {
        int idx = tid + i*256;
        int kk = idx >> 5, c4 = (idx & 31) * 4;
        pb[i] = *(const float4*)(Wr1 + (long)kk*H2D + bn + c4);
    }
    #pragma unroll
    for (int i = 0; i < 2; i++) {
        int idx = tid + i*256;
        int r = idx >> 2, kq = (idx & 3) * 4;
        As[kq+0][r]=pa[i].x; As[kq+1][r]=pa[i].y; As[kq+2][r]=pa[i].z; As[kq+3][r]=pa[i].w;
    }
    #pragma unroll
    for (int i = 0; i < 2; i++) {
        int idx = tid + i*256;
        int kk = idx >> 5, c4 = (idx & 31) * 4;
        *(float4*)(&Bs[kk][c4]) = pb[i];
    }
    __syncthreads();

    float acc[8][8] = {};
    for (int k0 = 0; k0 < Kdim; k0 += BK) {
        const bool has_next = (k0 + BK < Kdim);
        if (has_next) {
            #pragma unroll
            for (int i = 0; i < 2; i++) pa[i] = ldA(i, k0 + BK);
            #pragma unroll
            for (int i = 0; i < 2; i++) {
                int idx = tid + i*256;
                int kk = idx >> 5, c4 = (idx & 31) * 4;
                pb[i] = *(const float4*)(Wr1 + (long)(k0 + BK + kk)*H2D + bn + c4);
            }
        }
        #pragma unroll
        for (int kk = 0; kk < BK; kk++) {
            float4 a0 = *(const float4*)(&As[kk][ty*8]);
            float4 a1 = *(const float4*)(&As[kk][ty*8+4]);
            float4 b0 = *(const float4*)(&Bs[kk][tx*8]);
            float4 b1 = *(const float4*)(&Bs[kk][tx*8+4]);
            float av[8] = {a0.x,a0.y,a0.z,a0.w,a1.x,a1.y,a1.z,a1.w};
            float bv[8] = {b0.x,b0.y,b0.z,b0.w,b1.x,b1.y,b1.z,b1.w};
            #pragma unroll
            for (int i = 0; i < 8; i++)
                #pragma unroll
                for (int j = 0; j < 8; j++)
                    acc[i][j] += av[i] * bv[j];
        }
        __syncthreads();
        if (has_next) {
            #pragma unroll
            for (int i = 0; i < 2; i++) {
                int idx = tid + i*256;
                int r = idx >> 2, kq = (idx & 3) * 4;
                As[kq+0][r]=pa[i].x; As[kq+1][r]=pa[i].y; As[kq+2][r]=pa[i].z; As[kq+3][r]=pa[i].w;
            }
            #pragma unroll
            for (int i = 0; i < 2; i++) {
                int idx = tid + i*256;
                int kk = idx >> 5, c4 = (idx & 31) * 4;
                *(float4*)(&Bs[kk][c4]) = pb[i];
            }
        }
        __syncthreads();
    }

    float4 t0 = *(const float4*)(br1 + bn + tx*8);
    float4 t1 = *(const float4*)(br1 + bn + tx*8 + 4);
    float bias0[8] = {t0.x,t0.y,t0.z,t0.w,t1.x,t1.y,t1.z,t1.w};
    #pragma unroll
    for (int i = 0; i < 8; i++) {
        long row = bm + ty*8 + i;
        float v[8];
        #pragma unroll
        for (int j = 0; j < 8; j++) v[j] = fmaxf(acc[i][j] + bias0[j], 0.f);
        *(float4*)(R + row*H2D + bn + tx*8)     = make_float4(v[0],v[1],v[2],v[3]);
        *(float4*)(R + row*H2D + bn + tx*8 + 4) = make_float4(v[4],v[5],v[6],v[7]);
    }
}

// ============================================================
// top-8 + softmax + weighted gather of msgs -> agg
// ============================================================
__global__ __launch_bounds__(256) void topk_agg_kernel() {
    const int warp = threadIdx.x >> 5, lane = threadIdx.x & 31;
    const long row = (long)blockIdx.x * 8 + warp;  // < BN
    const int b = (int)(row >> 8);
    const float* srow = g_scores + row * NN;

    float v[8]; int idx[8]; unsigned used = 0;
    #pragma unroll
    for (int q = 0; q < 8; q++) { idx[q] = q*32 + lane; v[q] = srow[q*32 + lane]; }

    float topv[KK]; int topi[KK];
    #pragma unroll
    for (int it = 0; it < KK; it++) {
        float bv = -INFINITY; int bi = 1 << 30;
        #pragma unroll
        for (int q = 0; q < 8; q++) {
            bool ok = !((used >> q) & 1);
            if (ok && (v[q] > bv || (v[q] == bv && idx[q] < bi))) { bv = v[q]; bi = idx[q]; }
        }
        #pragma unroll
        for (int off = 16; off; off >>= 1) {
            float ov = __shfl_down_sync(0xffffffffu, bv, off);
            int   oi = __shfl_down_sync(0xffffffffu, bi, off);
            if (ov > bv || (ov == bv && oi < bi)) { bv = ov; bi = oi; }
        }
        bv = __shfl_sync(0xffffffffu, bv, 0);
        bi = __shfl_sync(0xffffffffu, bi, 0);
        topv[it] = bv; topi[it] = bi;
        #pragma unroll
        for (int q = 0; q < 8; q++) if (idx[q] == bi) used |= (1u << q);
    }

    float e[KK]; float s = 0.f;
    #pragma unroll
    for (int it = 0; it < KK; it++) { e[it] = expf(topv[it] - topv[0]); s += e[it]; }
    const float inv = 1.f / s;

    float a0 = 0.f, a1 = 0.f;
    #pragma unroll
    for (int it = 0; it < KK; it++) {
        const float* mrow = g_msgs + ((long)b * NN + topi[it]) * MSGD;
        float g = e[it] * inv;
        a0 += g * mrow[lane];
        a1 += g * mrow[lane + 32];
    }
    g_agg[row*MSGD + lane]      = a0;
    g_agg[row*MSGD + lane + 32] = a1;
}

// ============================================================
extern "C" void kernel_launch(void* const* d_in, const int* in_sizes, int n_in,
                              void* d_out, int out_size) {
    const float* obs  = (const float*)d_in[0];
    const float* W1   = (const float*)d_in[1];
    const float* b1   = (const float*)d_in[2];
    const float* W2   = (const float*)d_in[3];
    const float* b2   = (const float*)d_in[4];
    const float* Wc   = (const float*)d_in[5];
    const float* bc   = (const float*)d_in[6];
    const float* Wd   = (const float*)d_in[7];
    const float* bd   = (const float*)d_in[8];
    const float* Wbil = (const float*)d_in[9];
    const float* bbil = (const float*)d_in[10];
    const float* Wr1  = (const float*)d_in[11];
    const float* br1  = (const float*)d_in[12];
    const float* Wr2  = (const float*)d_in[13];
    const float* br2  = (const float*)d_in[14];
    float* out = (float*)d_out;

    float* h;      cudaGetSymbolAddress((void**)&h,      g_h);
    float* msgs;   cudaGetSymbolAddress((void**)&msgs,   g_msgs);
    float* tmp;    cudaGetSymbolAddress((void**)&tmp,    g_tmp);
    float* scores; cudaGetSymbolAddress((void**)&scores, g_scores);
    float* agg;    cudaGetSymbolAddress((void**)&agg,    g_agg);
    float* r;      cudaGetSymbolAddress((void**)&r,      g_r);
    float* W2p;    cudaGetSymbolAddress((void**)&W2p,    g_W2p);
    float* b2p;    cudaGetSymbolAddress((void**)&b2p,    g_b2p);

    prep_kernel<<<1, 128>>>(W2, b2, Wc, bc, Wd, bd);

    // h = relu(obs @ W1 + b1) : M=32768, N=128, K=256
    { dim3 grid(1, BN/BM); sgemm_nn<128, true, true><<<grid, 256>>>(obs, DD, W1, H1D, h, H1D, DD, b1); }

    // msgs = h @ W2p + b2p : M=32768, N=64, K=128
    { dim3 grid(1, BN/BM); sgemm_nn<64, false, true><<<grid, 128>>>(h, H1D, W2p, MSGD, msgs, MSGD, H1D, b2p); }

    // tmp = obs @ Wbil : M=32768, N=256, K=256
    { dim3 grid(2, BN/BM); sgemm_nn<128, false, false><<<grid, 256>>>(obs, DD, Wbil, DD, tmp, DD, DD, nullptr); }

    // scores[b] = tmp[b] @ obs[b]^T + bbil
    { dim3 grid(2, 2, BB); sgemm_nt_b<<<grid, 256>>>(tmp, obs, scores, bbil); }

    topk_agg_kernel<<<BN / 8, 256>>>();

    // r = relu([obs,agg] @ Wr1 + br1) : K=320
    { dim3 grid(2, BN/BM); sgemm_comb<<<grid, 256>>>(obs, agg, Wr1, br1, r); }

    // out = r @ Wr2 + br2 : M=32768, N=256, K=256
    { dim3 grid(2, BN/BM); sgemm_nn<128, false, true><<<grid, 256>>>(r, H2D, Wr2, DD, out, DD, H2D, br2); }
}

// round 4
// speedup vs baseline: 2.4736x; 2.4736x over previous
#include <cuda_runtime.h>
#include <math.h>
#include <stdint.h>

// Problem dims
#define BB    128
#define NNA   256
#define DD    256
#define MSGD  64
#define CDD   32
#define KKK   8
#define H1D   128
#define H2D   256
#define BNT   (BB*NNA)   // 32768

// -------- device scratch --------
__device__ float g_W2p[H1D*MSGD];
__device__ float g_b2p[MSGD];
__device__ float g_h   [(long)BNT*H1D];
__device__ float g_msgs[(long)BNT*MSGD];
__device__ float g_tmp [(long)BNT*DD];
__device__ float g_scores[(long)BB*NNA*NNA];
__device__ float g_agg [(long)BNT*MSGD];
__device__ float g_r   [(long)BNT*H2D];

// ============================================================
// tf32 helpers
// ============================================================
__device__ __forceinline__ float to_tf32(float x) {
    uint32_t u;
    asm("cvt.rna.tf32.f32 %0, %1;" : "=r"(u) : "f"(x));
    return __uint_as_float(u);
}

__device__ __forceinline__ void mma8(float* c, const uint32_t* a, const uint32_t* b) {
    asm volatile(
        "mma.sync.aligned.m16n8k8.row.col.f32.tf32.tf32.f32 "
        "{%0,%1,%2,%3}, {%4,%5,%6,%7}, {%8,%9}, {%0,%1,%2,%3};"
        : "+f"(c[0]), "+f"(c[1]), "+f"(c[2]), "+f"(c[3])
        : "r"(a[0]), "r"(a[1]), "r"(a[2]), "r"(a[3]), "r"(b[0]), "r"(b[1]));
}

// ============================================================
// 0) Compose W2' = W2@Wc@Wd, b2' = b2@Wc@Wd + bc@Wd + bd  (fp32)
// ============================================================
__global__ void prep_kernel(const float* __restrict__ W2, const float* __restrict__ b2,
                            const float* __restrict__ Wc, const float* __restrict__ bc,
                            const float* __restrict__ Wd, const float* __restrict__ bd) {
    __shared__ float bbuf[CDD];
    int t = threadIdx.x; // 128 threads
    float T[CDD];
    #pragma unroll
    for (int c = 0; c < CDD; c++) T[c] = 0.f;
    for (int m = 0; m < MSGD; m++) {
        float w = W2[t*MSGD + m];
        #pragma unroll
        for (int c = 0; c < CDD; c++) T[c] += w * Wc[m*CDD + c];
    }
    for (int mm = 0; mm < MSGD; mm++) {
        float acc = 0.f;
        #pragma unroll
        for (int c = 0; c < CDD; c++) acc += T[c] * Wd[c*MSGD + mm];
        g_W2p[t*MSGD + mm] = acc;
    }
    if (t < CDD) {
        float acc = bc[t];
        for (int m = 0; m < MSGD; m++) acc += b2[m] * Wc[m*CDD + t];
        bbuf[t] = acc;
    }
    __syncthreads();
    if (t < MSGD) {
        float acc = bd[t];
        #pragma unroll
        for (int c = 0; c < CDD; c++) acc += bbuf[c] * Wd[c*MSGD + t];
        g_b2p[t] = acc;
    }
}

// ============================================================
// tf32 MMA GEMM (NN): C = act(Acat @ B + bias)
//   A row-major (lda), virtual concat with A2 at column splitK
//   B row-major (ldb)
//   Block tile 128 x BNt x 16, 256 threads, warps WM x WN
// ============================================================
#define BM  128
#define BK  16

template<int BNt, int WM, int WN, bool RELU, bool BIASV>
__global__ __launch_bounds__(256, 2) void mma_nn(
    const float* __restrict__ A,  int lda,
    const float* __restrict__ A2, int lda2, int splitK,
    const float* __restrict__ Bw, int ldb,
    float* __restrict__ C, int ldc, int Kdim,
    const float* __restrict__ bias)
{
    static_assert(WM * WN == 8, "");
    constexpr int WTM = BM / WM;       // warp tile M
    constexpr int WTN = BNt / WN;      // warp tile N
    constexpr int MT  = WTM / 16;
    constexpr int NT  = WTN / 8;
    constexpr int APT = (BM * BK) / (4 * 256);   // float4 A loads / thread (=2)
    constexpr int BPT = (BK * BNt) / (4 * 256);  // float4 B loads / thread (2 or 1)

    __shared__ float As[BK][BM + 8];
    __shared__ float Bs[BK][BNt + 8];

    const int tid  = threadIdx.x;
    const int lane = tid & 31, wid = tid >> 5;
    const int lr = lane >> 2, lc = lane & 3;
    const int wm_off = (wid % WM) * WTM;
    const int wn_off = (wid / WM) * WTN;
    const long bm = (long)blockIdx.y * BM;
    const int  bn = blockIdx.x * BNt;

    float4 pa[APT], pb[BPT];

    auto loadA = [&](int i, int k0) -> float4 {
        int idx = tid + i * 256;
        int r = idx >> 2, kq = (idx & 3) * 4;
        int k = k0 + kq;
        const float* p = (k < splitK)
            ? (A  + (bm + r) * (long)lda  + k)
            : (A2 + (bm + r) * (long)lda2 + (k - splitK));
        return *(const float4*)p;
    };
    auto loadB = [&](int i, int k0) -> float4 {
        int idx = tid + i * 256;
        int kk = idx / (BNt / 4), c4 = (idx % (BNt / 4)) * 4;
        return *(const float4*)(Bw + (long)(k0 + kk) * ldb + bn + c4);
    };
    auto stsA = [&](int i, float4 v) {
        int idx = tid + i * 256;
        int r = idx >> 2, kq = (idx & 3) * 4;
        As[kq+0][r] = to_tf32(v.x); As[kq+1][r] = to_tf32(v.y);
        As[kq+2][r] = to_tf32(v.z); As[kq+3][r] = to_tf32(v.w);
    };
    auto stsB = [&](int i, float4 v) {
        int idx = tid + i * 256;
        int kk = idx / (BNt / 4), c4 = (idx % (BNt / 4)) * 4;
        float4 w = make_float4(to_tf32(v.x), to_tf32(v.y), to_tf32(v.z), to_tf32(v.w));
        *(float4*)(&Bs[kk][c4]) = w;
    };

    #pragma unroll
    for (int i = 0; i < APT; i++) pa[i] = loadA(i, 0);
    #pragma unroll
    for (int i = 0; i < BPT; i++) pb[i] = loadB(i, 0);
    #pragma unroll
    for (int i = 0; i < APT; i++) stsA(i, pa[i]);
    #pragma unroll
    for (int i = 0; i < BPT; i++) stsB(i, pb[i]);
    __syncthreads();

    float acc[MT][NT][4] = {};

    for (int k0 = 0; k0 < Kdim; k0 += BK) {
        const bool nxt = (k0 + BK < Kdim);
        if (nxt) {
            #pragma unroll
            for (int i = 0; i < APT; i++) pa[i] = loadA(i, k0 + BK);
            #pragma unroll
            for (int i = 0; i < BPT; i++) pb[i] = loadB(i, k0 + BK);
        }
        #pragma unroll
        for (int ks = 0; ks < BK; ks += 8) {
            uint32_t af[MT][4], bf[NT][2];
            #pragma unroll
            for (int mt = 0; mt < MT; mt++) {
                int m = wm_off + mt * 16 + lr;
                af[mt][0] = __float_as_uint(As[ks + lc    ][m    ]);
                af[mt][1] = __float_as_uint(As[ks + lc    ][m + 8]);
                af[mt][2] = __float_as_uint(As[ks + lc + 4][m    ]);
                af[mt][3] = __float_as_uint(As[ks + lc + 4][m + 8]);
            }
            #pragma unroll
            for (int nt = 0; nt < NT; nt++) {
                int n = wn_off + nt * 8 + lr;
                bf[nt][0] = __float_as_uint(Bs[ks + lc    ][n]);
                bf[nt][1] = __float_as_uint(Bs[ks + lc + 4][n]);
            }
            #pragma unroll
            for (int mt = 0; mt < MT; mt++)
                #pragma unroll
                for (int nt = 0; nt < NT; nt++)
                    mma8(acc[mt][nt], af[mt], bf[nt]);
        }
        __syncthreads();
        if (nxt) {
            #pragma unroll
            for (int i = 0; i < APT; i++) stsA(i, pa[i]);
            #pragma unroll
            for (int i = 0; i < BPT; i++) stsB(i, pb[i]);
        }
        __syncthreads();
    }

    // epilogue
    #pragma unroll
    for (int nt = 0; nt < NT; nt++) {
        int col = bn + wn_off + nt * 8 + 2 * lc;
        float b0 = 0.f, b1 = 0.f;
        if (BIASV) { b0 = bias[col]; b1 = bias[col + 1]; }
        #pragma unroll
        for (int mt = 0; mt < MT; mt++) {
            long row = bm + wm_off + mt * 16 + lr;
            float v0 = acc[mt][nt][0] + b0, v1 = acc[mt][nt][1] + b1;
            float v2 = acc[mt][nt][2] + b0, v3 = acc[mt][nt][3] + b1;
            if (RELU) {
                v0 = fmaxf(v0, 0.f); v1 = fmaxf(v1, 0.f);
                v2 = fmaxf(v2, 0.f); v3 = fmaxf(v3, 0.f);
            }
            *(float2*)(C + row * ldc + col)       = make_float2(v0, v1);
            *(float2*)(C + (row + 8) * ldc + col) = make_float2(v2, v3);
        }
    }
}

// ============================================================
// tf32 MMA GEMM (NT, batched): scores[b] = tmp[b] @ obs[b]^T + bbil
//   obs row-major [n][k] is exactly mma's col-major B.
// ============================================================
__global__ __launch_bounds__(256, 2) void mma_nt(
    const float* __restrict__ A, const float* __restrict__ Bm,
    float* __restrict__ C, const float* __restrict__ bbil)
{
    constexpr int WM = 2, WN = 4, WTM = 64, WTN = 32, MT = 4, NT = 4;
    __shared__ float As[BK][BM + 8];
    __shared__ float Bs[BM][20];       // [n][k], pitch 20 -> conflict-free frag reads

    const int tid  = threadIdx.x;
    const int lane = tid & 31, wid = tid >> 5;
    const int lr = lane >> 2, lc = lane & 3;
    const int wm_off = (wid % WM) * WTM;
    const int wn_off = (wid / WM) * WTN;
    const int b = blockIdx.z;
    const float* Ab = A  + (long)b * NNA * DD;
    const float* Bb = Bm + (long)b * NNA * DD;
    float* Cb = C + (long)b * NNA * NNA;
    const int bi = blockIdx.y * BM;
    const int bj = blockIdx.x * BM;

    float4 pa[2], pb[2];
    auto ldA = [&](int i, int k0) -> float4 {
        int idx = tid + i * 256;
        int r = idx >> 2, kq = (idx & 3) * 4;
        return *(const float4*)(Ab + (long)(bi + r) * DD + k0 + kq);
    };
    auto ldB = [&](int i, int k0) -> float4 {
        int idx = tid + i * 256;
        int r = idx >> 2, kq = (idx & 3) * 4;
        return *(const float4*)(Bb + (long)(bj + r) * DD + k0 + kq);
    };
    auto stA = [&](int i, float4 v) {
        int idx = tid + i * 256;
        int r = idx >> 2, kq = (idx & 3) * 4;
        As[kq+0][r] = to_tf32(v.x); As[kq+1][r] = to_tf32(v.y);
        As[kq+2][r] = to_tf32(v.z); As[kq+3][r] = to_tf32(v.w);
    };
    auto stB = [&](int i, float4 v) {
        int idx = tid + i * 256;
        int r = idx >> 2, kq = (idx & 3) * 4;
        float4 w = make_float4(to_tf32(v.x), to_tf32(v.y), to_tf32(v.z), to_tf32(v.w));
        *(float4*)(&Bs[r][kq]) = w;
    };

    #pragma unroll
    for (int i = 0; i < 2; i++) { pa[i] = ldA(i, 0); pb[i] = ldB(i, 0); }
    #pragma unroll
    for (int i = 0; i < 2; i++) { stA(i, pa[i]); stB(i, pb[i]); }
    __syncthreads();

    float acc[MT][NT][4] = {};

    for (int k0 = 0; k0 < DD; k0 += BK) {
        const bool nxt = (k0 + BK < DD);
        if (nxt) {
            #pragma unroll
            for (int i = 0; i < 2; i++) { pa[i] = ldA(i, k0 + BK); pb[i] = ldB(i, k0 + BK); }
        }
        #pragma unroll
        for (int ks = 0; ks < BK; ks += 8) {
            uint32_t af[MT][4], bf[NT][2];
            #pragma unroll
            for (int mt = 0; mt < MT; mt++) {
                int m = wm_off + mt * 16 + lr;
                af[mt][0] = __float_as_uint(As[ks + lc    ][m    ]);
                af[mt][1] = __float_as_uint(As[ks + lc    ][m + 8]);
                af[mt][2] = __float_as_uint(As[ks + lc + 4][m    ]);
                af[mt][3] = __float_as_uint(As[ks + lc + 4][m + 8]);
            }
            #pragma unroll
            for (int nt = 0; nt < NT; nt++) {
                int n = wn_off + nt * 8 + lr;
                bf[nt][0] = __float_as_uint(Bs[n][ks + lc    ]);
                bf[nt][1] = __float_as_uint(Bs[n][ks + lc + 4]);
            }
            #pragma unroll
            for (int mt = 0; mt < MT; mt++)
                #pragma unroll
                for (int nt = 0; nt < NT; nt++)
                    mma8(acc[mt][nt], af[mt], bf[nt]);
        }
        __syncthreads();
        if (nxt) {
            #pragma unroll
            for (int i = 0; i < 2; i++) { stA(i, pa[i]); stB(i, pb[i]); }
        }
        __syncthreads();
    }

    const float bv = *bbil;
    #pragma unroll
    for (int nt = 0; nt < NT; nt++) {
        int col = bj + wn_off + nt * 8 + 2 * lc;
        #pragma unroll
        for (int mt = 0; mt < MT; mt++) {
            int row = bi + wm_off + mt * 16 + lr;
            *(float2*)(Cb + (long)row * NNA + col) =
                make_float2(acc[mt][nt][0] + bv, acc[mt][nt][1] + bv);
            *(float2*)(Cb + (long)(row + 8) * NNA + col) =
                make_float2(acc[mt][nt][2] + bv, acc[mt][nt][3] + bv);
        }
    }
}

// ============================================================
// top-8 + softmax + weighted gather of msgs -> agg (fp32, exact)
// ============================================================
__global__ __launch_bounds__(256) void topk_agg_kernel() {
    const int warp = threadIdx.x >> 5, lane = threadIdx.x & 31;
    const long row = (long)blockIdx.x * 8 + warp;
    const int b = (int)(row >> 8);
    const float* srow = g_scores + row * NNA;

    float v[8]; int idx[8]; unsigned used = 0;
    #pragma unroll
    for (int q = 0; q < 8; q++) { idx[q] = q*32 + lane; v[q] = srow[q*32 + lane]; }

    float topv[KKK]; int topi[KKK];
    #pragma unroll
    for (int it = 0; it < KKK; it++) {
        float bv = -INFINITY; int bi = 1 << 30;
        #pragma unroll
        for (int q = 0; q < 8; q++) {
            bool ok = !((used >> q) & 1);
            if (ok && (v[q] > bv || (v[q] == bv && idx[q] < bi))) { bv = v[q]; bi = idx[q]; }
        }
        #pragma unroll
        for (int off = 16; off; off >>= 1) {
            float ov = __shfl_down_sync(0xffffffffu, bv, off);
            int   oi = __shfl_down_sync(0xffffffffu, bi, off);
            if (ov > bv || (ov == bv && oi < bi)) { bv = ov; bi = oi; }
        }
        bv = __shfl_sync(0xffffffffu, bv, 0);
        bi = __shfl_sync(0xffffffffu, bi, 0);
        topv[it] = bv; topi[it] = bi;
        #pragma unroll
        for (int q = 0; q < 8; q++) if (idx[q] == bi) used |= (1u << q);
    }

    float e[KKK]; float s = 0.f;
    #pragma unroll
    for (int it = 0; it < KKK; it++) { e[it] = expf(topv[it] - topv[0]); s += e[it]; }
    const float inv = 1.f / s;

    float a0 = 0.f, a1 = 0.f;
    #pragma unroll
    for (int it = 0; it < KKK; it++) {
        const float* mrow = g_msgs + ((long)b * NNA + topi[it]) * MSGD;
        float g = e[it] * inv;
        a0 += g * mrow[lane];
        a1 += g * mrow[lane + 32];
    }
    g_agg[row*MSGD + lane]      = a0;
    g_agg[row*MSGD + lane + 32] = a1;
}

// ============================================================
extern "C" void kernel_launch(void* const* d_in, const int* in_sizes, int n_in,
                              void* d_out, int out_size) {
    const float* obs  = (const float*)d_in[0];
    const float* W1   = (const float*)d_in[1];
    const float* b1   = (const float*)d_in[2];
    const float* W2   = (const float*)d_in[3];
    const float* b2   = (const float*)d_in[4];
    const float* Wc   = (const float*)d_in[5];
    const float* bc   = (const float*)d_in[6];
    const float* Wd   = (const float*)d_in[7];
    const float* bd   = (const float*)d_in[8];
    const float* Wbil = (const float*)d_in[9];
    const float* bbil = (const float*)d_in[10];
    const float* Wr1  = (const float*)d_in[11];
    const float* br1  = (const float*)d_in[12];
    const float* Wr2  = (const float*)d_in[13];
    const float* br2  = (const float*)d_in[14];
    float* out = (float*)d_out;

    float* h;      cudaGetSymbolAddress((void**)&h,      g_h);
    float* msgs;   cudaGetSymbolAddress((void**)&msgs,   g_msgs);
    float* tmp;    cudaGetSymbolAddress((void**)&tmp,    g_tmp);
    float* scores; cudaGetSymbolAddress((void**)&scores, g_scores);
    float* agg;    cudaGetSymbolAddress((void**)&agg,    g_agg);
    float* r;      cudaGetSymbolAddress((void**)&r,      g_r);
    float* W2p;    cudaGetSymbolAddress((void**)&W2p,    g_W2p);
    float* b2p;    cudaGetSymbolAddress((void**)&b2p,    g_b2p);

    prep_kernel<<<1, 128>>>(W2, b2, Wc, bc, Wd, bd);

    // h = relu(obs @ W1 + b1) : M=32768, N=128, K=256
    mma_nn<128, 2, 4, true, true><<<dim3(1, BNT/BM), 256>>>(
        obs, DD, obs, DD, DD, W1, H1D, h, H1D, DD, b1);

    // msgs = h @ W2p + b2p : M=32768, N=64, K=128
    mma_nn<64, 4, 2, false, true><<<dim3(1, BNT/BM), 256>>>(
        h, H1D, h, H1D, H1D, W2p, MSGD, msgs, MSGD, H1D, b2p);

    // tmp = obs @ Wbil : M=32768, N=256, K=256
    mma_nn<128, 2, 4, false, false><<<dim3(2, BNT/BM), 256>>>(
        obs, DD, obs, DD, DD, Wbil, DD, tmp, DD, DD, nullptr);

    // scores[b] = tmp[b] @ obs[b]^T + bbil
    mma_nt<<<dim3(2, 2, BB), 256>>>(tmp, obs, scores, bbil);

    topk_agg_kernel<<<BNT / 8, 256>>>();

    // r = relu([obs,agg] @ Wr1 + br1) : K=320 (virtual concat, split at 256)
    mma_nn<128, 2, 4, true, true><<<dim3(2, BNT/BM), 256>>>(
        obs, DD, agg, MSGD, DD, Wr1, H2D, r, H2D, DD + MSGD, br1);

    // out = r @ Wr2 + br2 : M=32768, N=256, K=256
    mma_nn<128, 2, 4, false, true><<<dim3(2, BNT/BM), 256>>>(
        r, H2D, r, H2D, H2D, Wr2, DD, out, DD, H2D, br2);
}

// round 5
// speedup vs baseline: 2.5484x; 1.0303x over previous
#include <cuda_runtime.h>
#include <math.h>
#include <stdint.h>

// Problem dims
#define BB    128
#define NNA   256
#define DD    256
#define MSGD  64
#define CDD   32
#define KKK   8
#define H1D   128
#define H2D   256
#define BNT   (BB*NNA)   // 32768

// -------- device scratch --------
__device__ float g_W2p[H1D*MSGD];
__device__ float g_b2p[MSGD];
__device__ float g_obst[(long)BNT*DD];      // tf32-rounded obs
__device__ float g_W1t [DD*H1D];
__device__ float g_Wbilt[DD*DD];
__device__ float g_Wr1t[(DD+MSGD)*H2D];
__device__ float g_Wr2t[H2D*DD];
__device__ float g_h   [(long)BNT*H1D];
__device__ float g_msgs[(long)BNT*MSGD];
__device__ float g_tmp [(long)BNT*DD];
__device__ float g_scores[(long)BB*NNA*NNA];
__device__ float g_agg [(long)BNT*MSGD];
__device__ float g_r   [(long)BNT*H2D];

// ============================================================
// helpers
// ============================================================
__device__ __forceinline__ float to_tf32(float x) {
    uint32_t u;
    asm("cvt.rna.tf32.f32 %0, %1;" : "=r"(u) : "f"(x));
    return __uint_as_float(u);
}

__device__ __forceinline__ void mma8(float* c, const uint32_t* a, const uint32_t* b) {
    asm volatile(
        "mma.sync.aligned.m16n8k8.row.col.f32.tf32.tf32.f32 "
        "{%0,%1,%2,%3}, {%4,%5,%6,%7}, {%8,%9}, {%0,%1,%2,%3};"
        : "+f"(c[0]), "+f"(c[1]), "+f"(c[2]), "+f"(c[3])
        : "r"(a[0]), "r"(a[1]), "r"(a[2]), "r"(a[3]), "r"(b[0]), "r"(b[1]));
}

__device__ __forceinline__ void cp16(void* smem_dst, const void* gmem_src) {
    uint32_t s = (uint32_t)__cvta_generic_to_shared(smem_dst);
    asm volatile("cp.async.cg.shared.global [%0], [%1], 16;" :: "r"(s), "l"(gmem_src));
}
#define CP_COMMIT() asm volatile("cp.async.commit_group;")
#define CP_WAIT0()  asm volatile("cp.async.wait_group 0;")

// ============================================================
// conversion kernels (fp32 -> tf32-rounded fp32)
// ============================================================
__global__ void cvt_kernel(const float* __restrict__ src, float* __restrict__ dst, int n4) {
    int i = blockIdx.x * blockDim.x + threadIdx.x;
    if (i < n4) {
        float4 v = ((const float4*)src)[i];
        ((float4*)dst)[i] = make_float4(to_tf32(v.x), to_tf32(v.y), to_tf32(v.z), to_tf32(v.w));
    }
}

__global__ void cvt_weights(const float* __restrict__ W1, const float* __restrict__ Wbil,
                            const float* __restrict__ Wr1, const float* __restrict__ Wr2) {
    int i = blockIdx.x * blockDim.x + threadIdx.x;
    if (i < DD*H1D/4) {
        float4 v = ((const float4*)W1)[i];
        ((float4*)g_W1t)[i] = make_float4(to_tf32(v.x), to_tf32(v.y), to_tf32(v.z), to_tf32(v.w));
    }
    if (i < DD*DD/4) {
        float4 v = ((const float4*)Wbil)[i];
        ((float4*)g_Wbilt)[i] = make_float4(to_tf32(v.x), to_tf32(v.y), to_tf32(v.z), to_tf32(v.w));
    }
    if (i < (DD+MSGD)*H2D/4) {
        float4 v = ((const float4*)Wr1)[i];
        ((float4*)g_Wr1t)[i] = make_float4(to_tf32(v.x), to_tf32(v.y), to_tf32(v.z), to_tf32(v.w));
    }
    if (i < H2D*DD/4) {
        float4 v = ((const float4*)Wr2)[i];
        ((float4*)g_Wr2t)[i] = make_float4(to_tf32(v.x), to_tf32(v.y), to_tf32(v.z), to_tf32(v.w));
    }
}

// ============================================================
// 0) Compose W2' = W2@Wc@Wd (tf32-rounded), b2' composed (fp32)
// ============================================================
__global__ void prep_kernel(const float* __restrict__ W2, const float* __restrict__ b2,
                            const float* __restrict__ Wc, const float* __restrict__ bc,
                            const float* __restrict__ Wd, const float* __restrict__ bd) {
    __shared__ float bbuf[CDD];
    int t = threadIdx.x; // 128 threads
    float T[CDD];
    #pragma unroll
    for (int c = 0; c < CDD; c++) T[c] = 0.f;
    for (int m = 0; m < MSGD; m++) {
        float w = W2[t*MSGD + m];
        #pragma unroll
        for (int c = 0; c < CDD; c++) T[c] += w * Wc[m*CDD + c];
    }
    for (int mm = 0; mm < MSGD; mm++) {
        float acc = 0.f;
        #pragma unroll
        for (int c = 0; c < CDD; c++) acc += T[c] * Wd[c*MSGD + mm];
        g_W2p[t*MSGD + mm] = to_tf32(acc);
    }
    if (t < CDD) {
        float acc = bc[t];
        for (int m = 0; m < MSGD; m++) acc += b2[m] * Wc[m*CDD + t];
        bbuf[t] = acc;
    }
    __syncthreads();
    if (t < MSGD) {
        float acc = bd[t];
        #pragma unroll
        for (int c = 0; c < CDD; c++) acc += bbuf[c] * Wd[c*MSGD + t];
        g_b2p[t] = acc;
    }
}

// ============================================================
// tf32 MMA GEMM (NN) with cp.async 2-stage pipeline
//   A row-major (lda), virtual concat with A2 at column splitK (tf32-pre-rounded)
//   B row-major (ldb) tf32-pre-rounded
// ============================================================
#define BM  128
#define BK  16
#define AP  20   // A smem pitch ([m][k])

template<int BNt, int WM, int WN, bool RELU, bool BIASV, bool CVTOUT>
__global__ __launch_bounds__(256, 2) void mma_nn(
    const float* __restrict__ A,  int lda,
    const float* __restrict__ A2, int lda2, int splitK,
    const float* __restrict__ Bw, int ldb,
    float* __restrict__ C, int ldc, int Kdim,
    const float* __restrict__ bias)
{
    static_assert(WM * WN == 8, "");
    constexpr int WTM = BM / WM, WTN = BNt / WN;
    constexpr int MT = WTM / 16, NT = WTN / 8;
    constexpr int BP = BNt + 8;
    constexpr int BCNT = (BK * BNt) / (4 * 256);  // B cp.async per thread (2 or 1)

    __shared__ float As[2][BM][AP];
    __shared__ float Bs[2][BK][BP];

    const int tid  = threadIdx.x;
    const int lane = tid & 31, wid = tid >> 5;
    const int lr = lane >> 2, lc = lane & 3;
    const int wm_off = (wid % WM) * WTM;
    const int wn_off = (wid / WM) * WTN;
    const long bm = (long)blockIdx.y * BM;
    const int  bn = blockIdx.x * BNt;

    const int ar = tid >> 2, akq = (tid & 3) * 4;  // A cp.async coords (i stride 64 rows)

    auto issueA = [&](int st, int k0) {
        #pragma unroll
        for (int i = 0; i < 2; i++) {
            int r = ar + i * 64;
            int k = k0 + akq;
            const float* src = (k < splitK)
                ? (A  + (bm + r) * (long)lda  + k)
                : (A2 + (bm + r) * (long)lda2 + (k - splitK));
            cp16(&As[st][r][akq], src);
        }
    };
    auto issueB = [&](int st, int k0) {
        #pragma unroll
        for (int i = 0; i < BCNT; i++) {
            int idx = tid + i * 256;
            int kk = idx / (BNt / 4), c4 = (idx % (BNt / 4)) * 4;
            cp16(&Bs[st][kk][c4], Bw + (long)(k0 + kk) * ldb + bn + c4);
        }
    };

    issueA(0, 0); issueB(0, 0); CP_COMMIT();

    float acc[MT][NT][4] = {};
    int st = 0;
    for (int k0 = 0; k0 < Kdim; k0 += BK) {
        CP_WAIT0();
        __syncthreads();
        if (k0 + BK < Kdim) { issueA(st ^ 1, k0 + BK); issueB(st ^ 1, k0 + BK); CP_COMMIT(); }
        #pragma unroll
        for (int ks = 0; ks < BK; ks += 8) {
            uint32_t af[MT][4], bf[NT][2];
            #pragma unroll
            for (int mt = 0; mt < MT; mt++) {
                int m = wm_off + mt * 16 + lr;
                af[mt][0] = __float_as_uint(As[st][m    ][ks + lc    ]);
                af[mt][1] = __float_as_uint(As[st][m + 8][ks + lc    ]);
                af[mt][2] = __float_as_uint(As[st][m    ][ks + lc + 4]);
                af[mt][3] = __float_as_uint(As[st][m + 8][ks + lc + 4]);
            }
            #pragma unroll
            for (int nt = 0; nt < NT; nt++) {
                int n = wn_off + nt * 8 + lr;
                bf[nt][0] = __float_as_uint(Bs[st][ks + lc    ][n]);
                bf[nt][1] = __float_as_uint(Bs[st][ks + lc + 4][n]);
            }
            #pragma unroll
            for (int mt = 0; mt < MT; mt++)
                #pragma unroll
                for (int nt = 0; nt < NT; nt++)
                    mma8(acc[mt][nt], af[mt], bf[nt]);
        }
        st ^= 1;
    }

    // epilogue
    #pragma unroll
    for (int nt = 0; nt < NT; nt++) {
        int col = bn + wn_off + nt * 8 + 2 * lc;
        float b0 = 0.f, b1 = 0.f;
        if (BIASV) { b0 = bias[col]; b1 = bias[col + 1]; }
        #pragma unroll
        for (int mt = 0; mt < MT; mt++) {
            long row = bm + wm_off + mt * 16 + lr;
            float v0 = acc[mt][nt][0] + b0, v1 = acc[mt][nt][1] + b1;
            float v2 = acc[mt][nt][2] + b0, v3 = acc[mt][nt][3] + b1;
            if (RELU) {
                v0 = fmaxf(v0, 0.f); v1 = fmaxf(v1, 0.f);
                v2 = fmaxf(v2, 0.f); v3 = fmaxf(v3, 0.f);
            }
            if (CVTOUT) {
                v0 = to_tf32(v0); v1 = to_tf32(v1);
                v2 = to_tf32(v2); v3 = to_tf32(v3);
            }
            *(float2*)(C + row * ldc + col)       = make_float2(v0, v1);
            *(float2*)(C + (row + 8) * ldc + col) = make_float2(v2, v3);
        }
    }
}

// ============================================================
// tf32 MMA GEMM (NT, batched) with cp.async 2-stage:
//   scores[b] = tmp[b] @ obst[b]^T + bbil
// ============================================================
__global__ __launch_bounds__(256, 2) void mma_nt(
    const float* __restrict__ A, const float* __restrict__ Bm,
    float* __restrict__ C, const float* __restrict__ bbil)
{
    constexpr int WM = 2, WTM = 64, WTN = 32, MT = 4, NT = 4;
    __shared__ float As[2][BM][AP];
    __shared__ float Bs[2][BM][AP];   // [n][k]

    const int tid  = threadIdx.x;
    const int lane = tid & 31, wid = tid >> 5;
    const int lr = lane >> 2, lc = lane & 3;
    const int wm_off = (wid % WM) * WTM;
    const int wn_off = (wid / WM) * WTN;
    const int b = blockIdx.z;
    const float* Ab = A  + (long)b * NNA * DD;
    const float* Bb = Bm + (long)b * NNA * DD;
    float* Cb = C + (long)b * NNA * NNA;
    const int bi = blockIdx.y * BM;
    const int bj = blockIdx.x * BM;

    const int ar = tid >> 2, akq = (tid & 3) * 4;

    auto issue = [&](int st, int k0) {
        #pragma unroll
        for (int i = 0; i < 2; i++) {
            int r = ar + i * 64;
            cp16(&As[st][r][akq], Ab + (long)(bi + r) * DD + k0 + akq);
            cp16(&Bs[st][r][akq], Bb + (long)(bj + r) * DD + k0 + akq);
        }
    };

    issue(0, 0); CP_COMMIT();

    float acc[MT][NT][4] = {};
    int st = 0;
    for (int k0 = 0; k0 < DD; k0 += BK) {
        CP_WAIT0();
        __syncthreads();
        if (k0 + BK < DD) { issue(st ^ 1, k0 + BK); CP_COMMIT(); }
        #pragma unroll
        for (int ks = 0; ks < BK; ks += 8) {
            uint32_t af[MT][4], bf[NT][2];
            #pragma unroll
            for (int mt = 0; mt < MT; mt++) {
                int m = wm_off + mt * 16 + lr;
                af[mt][0] = __float_as_uint(As[st][m    ][ks + lc    ]);
                af[mt][1] = __float_as_uint(As[st][m + 8][ks + lc    ]);
                af[mt][2] = __float_as_uint(As[st][m    ][ks + lc + 4]);
                af[mt][3] = __float_as_uint(As[st][m + 8][ks + lc + 4]);
            }
            #pragma unroll
            for (int nt = 0; nt < NT; nt++) {
                int n = wn_off + nt * 8 + lr;
                bf[nt][0] = __float_as_uint(Bs[st][n][ks + lc    ]);
                bf[nt][1] = __float_as_uint(Bs[st][n][ks + lc + 4]);
            }
            #pragma unroll
            for (int mt = 0; mt < MT; mt++)
                #pragma unroll
                for (int nt = 0; nt < NT; nt++)
                    mma8(acc[mt][nt], af[mt], bf[nt]);
        }
        st ^= 1;
    }

    const float bv = *bbil;
    #pragma unroll
    for (int nt = 0; nt < NT; nt++) {
        int col = bj + wn_off + nt * 8 + 2 * lc;
        #pragma unroll
        for (int mt = 0; mt < MT; mt++) {
            int row = bi + wm_off + mt * 16 + lr;
            *(float2*)(Cb + (long)row * NNA + col) =
                make_float2(acc[mt][nt][0] + bv, acc[mt][nt][1] + bv);
            *(float2*)(Cb + (long)(row + 8) * NNA + col) =
                make_float2(acc[mt][nt][2] + bv, acc[mt][nt][3] + bv);
        }
    }
}

// ============================================================
// top-8 + softmax + weighted gather of msgs -> agg (fp32 exact,
// agg stored tf32-rounded for downstream GEMM)
// ============================================================
__global__ __launch_bounds__(256) void topk_agg_kernel() {
    const int warp = threadIdx.x >> 5, lane = threadIdx.x & 31;
    const long row = (long)blockIdx.x * 8 + warp;
    const int b = (int)(row >> 8);
    const float* srow = g_scores + row * NNA;

    float v[8]; int idx[8]; unsigned used = 0;
    #pragma unroll
    for (int q = 0; q < 8; q++) { idx[q] = q*32 + lane; v[q] = srow[q*32 + lane]; }

    float topv[KKK]; int topi[KKK];
    #pragma unroll
    for (int it = 0; it < KKK; it++) {
        float bv = -INFINITY; int bi = 1 << 30;
        #pragma unroll
        for (int q = 0; q < 8; q++) {
            bool ok = !((used >> q) & 1);
            if (ok && (v[q] > bv || (v[q] == bv && idx[q] < bi))) { bv = v[q]; bi = idx[q]; }
        }
        #pragma unroll
        for (int off = 16; off; off >>= 1) {
            float ov = __shfl_down_sync(0xffffffffu, bv, off);
            int   oi = __shfl_down_sync(0xffffffffu, bi, off);
            if (ov > bv || (ov == bv && oi < bi)) { bv = ov; bi = oi; }
        }
        bv = __shfl_sync(0xffffffffu, bv, 0);
        bi = __shfl_sync(0xffffffffu, bi, 0);
        topv[it] = bv; topi[it] = bi;
        #pragma unroll
        for (int q = 0; q < 8; q++) if (idx[q] == bi) used |= (1u << q);
    }

    float e[KKK]; float s = 0.f;
    #pragma unroll
    for (int it = 0; it < KKK; it++) { e[it] = expf(topv[it] - topv[0]); s += e[it]; }
    const float inv = 1.f / s;

    float a0 = 0.f, a1 = 0.f;
    #pragma unroll
    for (int it = 0; it < KKK; it++) {
        const float* mrow = g_msgs + ((long)b * NNA + topi[it]) * MSGD;
        float g = e[it] * inv;
        a0 += g * mrow[lane];
        a1 += g * mrow[lane + 32];
    }
    g_agg[row*MSGD + lane]      = to_tf32(a0);
    g_agg[row*MSGD + lane + 32] = to_tf32(a1);
}

// ============================================================
extern "C" void kernel_launch(void* const* d_in, const int* in_sizes, int n_in,
                              void* d_out, int out_size) {
    const float* obs  = (const float*)d_in[0];
    const float* W1   = (const float*)d_in[1];
    const float* b1   = (const float*)d_in[2];
    const float* W2   = (const float*)d_in[3];
    const float* b2   = (const float*)d_in[4];
    const float* Wc   = (const float*)d_in[5];
    const float* bc   = (const float*)d_in[6];
    const float* Wd   = (const float*)d_in[7];
    const float* bd   = (const float*)d_in[8];
    const float* Wbil = (const float*)d_in[9];
    const float* bbil = (const float*)d_in[10];
    const float* Wr1  = (const float*)d_in[11];
    const float* br1  = (const float*)d_in[12];
    const float* Wr2  = (const float*)d_in[13];
    const float* br2  = (const float*)d_in[14];
    float* out = (float*)d_out;

    float* obst;   cudaGetSymbolAddress((void**)&obst,   g_obst);
    float* W1t;    cudaGetSymbolAddress((void**)&W1t,    g_W1t);
    float* Wbilt;  cudaGetSymbolAddress((void**)&Wbilt,  g_Wbilt);
    float* Wr1t;   cudaGetSymbolAddress((void**)&Wr1t,   g_Wr1t);
    float* Wr2t;   cudaGetSymbolAddress((void**)&Wr2t,   g_Wr2t);
    float* h;      cudaGetSymbolAddress((void**)&h,      g_h);
    float* msgs;   cudaGetSymbolAddress((void**)&msgs,   g_msgs);
    float* tmp;    cudaGetSymbolAddress((void**)&tmp,    g_tmp);
    float* scores; cudaGetSymbolAddress((void**)&scores, g_scores);
    float* agg;    cudaGetSymbolAddress((void**)&agg,    g_agg);
    float* r;      cudaGetSymbolAddress((void**)&r,      g_r);
    float* W2p;    cudaGetSymbolAddress((void**)&W2p,    g_W2p);
    float* b2p;    cudaGetSymbolAddress((void**)&b2p,    g_b2p);

    // prologue: tf32-round obs + weights, compose W2'
    cvt_kernel<<<(BNT*DD/4 + 255)/256, 256>>>(obs, obst, BNT*DD/4);
    cvt_weights<<<((DD+MSGD)*H2D/4 + 255)/256, 256>>>(W1, Wbil, Wr1, Wr2);
    prep_kernel<<<1, 128>>>(W2, b2, Wc, bc, Wd, bd);

    // h = relu(obst @ W1t + b1), output tf32-rounded
    mma_nn<128, 2, 4, true, true, true><<<dim3(1, BNT/BM), 256>>>(
        obst, DD, obst, DD, DD, W1t, H1D, h, H1D, DD, b1);

    // msgs = h @ W2p + b2p, fp32 out (consumed by fp32 gather)
    mma_nn<64, 4, 2, false, true, false><<<dim3(1, BNT/BM), 256>>>(
        h, H1D, h, H1D, H1D, W2p, MSGD, msgs, MSGD, H1D, b2p);

    // tmp = obst @ Wbilt, output tf32-rounded
    mma_nn<128, 2, 4, false, false, true><<<dim3(2, BNT/BM), 256>>>(
        obst, DD, obst, DD, DD, Wbilt, DD, tmp, DD, DD, nullptr);

    // scores[b] = tmp[b] @ obst[b]^T + bbil (fp32 out)
    mma_nt<<<dim3(2, 2, BB), 256>>>(tmp, obst, scores, bbil);

    topk_agg_kernel<<<BNT / 8, 256>>>();

    // r = relu([obst,agg] @ Wr1t + br1), K=320, output tf32-rounded
    mma_nn<128, 2, 4, true, true, true><<<dim3(2, BNT/BM), 256>>>(
        obst, DD, agg, MSGD, DD, Wr1t, H2D, r, H2D, DD + MSGD, br1);

    // out = r @ Wr2t + br2 (fp32 out)
    mma_nn<128, 2, 4, false, true, false><<<dim3(2, BNT/BM), 256>>>(
        r, H2D, r, H2D, H2D, Wr2t, DD, out, DD, H2D, br2);
}